// round 10
// baseline (speedup 1.0000x reference)
#include <cuda_runtime.h>
#include <cuda_fp16.h>
#include <mma.h>
#include <cstdint>

using namespace nvcuda;

#define TSTEPS 512
#define BATCH  128
#define HID    1024
#define NG     4096
#define NLAYER 2
#define NCTA_R 128
#define THR_R  256   // 8 warps: 4 mquad x 2 khalf

// ---------------- device scratch ----------------
__device__ float  g_gatesT[(size_t)TSTEPS * NG * BATCH];          // [t][col][b]
__device__ __align__(16) __half g_hseq16[(size_t)TSTEPS * BATCH * HID];
__device__ __align__(16) __half g_h16[2][BATCH * HID];            // ping-pong h
__device__ unsigned int g_count;

// ---------------- recurrence smem layout (bytes) ----------------
#define SM_W     0
#define SM_A     81920
#define SM_ABUF  34816
#define SM_G     186368
#define SM_BIAS  227328
#define SM_TOTAL 227584

__device__ __forceinline__ uint32_t smem_u32(const void* p) {
    uint32_t a;
    asm("{ .reg .u64 t; cvta.to.shared.u64 t, %1; cvt.u32.u64 %0, t; }" : "=r"(a) : "l"(p));
    return a;
}
__device__ __forceinline__ void cp16(uint32_t dst, const void* src) {
    asm volatile("cp.async.cg.shared.global [%0], [%1], 16;" :: "r"(dst), "l"(src));
}
#define CP_COMMIT() asm volatile("cp.async.commit_group;" ::: "memory")
#define CP_WAIT1()  asm volatile("cp.async.wait_group 1;" ::: "memory")
#define CP_WAIT0()  asm volatile("cp.async.wait_group 0;" ::: "memory")

__device__ __forceinline__ void rel_add1(unsigned int* p) {
    asm volatile("red.release.gpu.global.add.u32 [%0], 1;" :: "l"(p) : "memory");
}
__device__ __forceinline__ unsigned int acq_ld(const unsigned int* p) {
    unsigned int v;
    asm volatile("ld.acquire.gpu.global.u32 %0, [%1];" : "=r"(v) : "l"(p) : "memory");
    return v;
}

__device__ __forceinline__ float sigf(float x) { return 1.f / (1.f + __expf(-x)); }
__device__ __forceinline__ uint32_t packh2(float a, float b) {
    return (uint32_t)__half_as_ushort(__float2half_rn(a)) |
           ((uint32_t)__half_as_ushort(__float2half_rn(b)) << 16);
}

// =================================================================================
// Input GEMM (unchanged — controlled experiment on the recurrence)
// =================================================================================
template<bool AHALF>
__global__ void __launch_bounds__(256) gemm_input(const void* __restrict__ Av,
                                                  const float* __restrict__ W,
                                                  float* __restrict__ CT)
{
    __shared__ __half As[128][40];
    __shared__ __half Bs[32][136];

    const int tid  = threadIdx.x;
    const int warp = tid >> 5;
    const int wm = warp >> 2;
    const int wn = warp & 3;
    const int bm = blockIdx.y;
    const int bn = blockIdx.x;

    const int arow = tid >> 1, acol = (tid & 1) * 16;
    const int brow = tid >> 3, bcol = (tid & 7) * 16;

    const float*  Af = (const float*) Av;
    const __half* Ah = (const __half*)Av;
    const size_t  a_off = (size_t)(bm * 128 + arow) * 1024 + acol;
    const float*  Wg = W + (size_t)brow * NG + bn * 128 + bcol;

    wmma::fragment<wmma::accumulator, 16, 16, 16, float> acc[4][2];
#pragma unroll
    for (int i = 0; i < 4; i++)
#pragma unroll
        for (int j = 0; j < 2; j++) wmma::fill_fragment(acc[i][j], 0.f);

    float4 ra[4]; uint4 ra16[2]; float4 rb[4];
    if (AHALF) {
        ra16[0] = ((const uint4*)(Ah + a_off))[0];
        ra16[1] = ((const uint4*)(Ah + a_off))[1];
    } else {
#pragma unroll
        for (int i = 0; i < 4; i++) ra[i] = *(const float4*)(Af + a_off + i * 4);
    }
#pragma unroll
    for (int i = 0; i < 4; i++) rb[i] = *(const float4*)(Wg + i * 4);

    for (int k0 = 0; k0 < 1024; k0 += 32) {
        __syncthreads();
        if (AHALF) {
            *(uint4*)&As[arow][acol]     = ra16[0];
            *(uint4*)&As[arow][acol + 8] = ra16[1];
        } else {
            *(uint4*)&As[arow][acol] = make_uint4(
                packh2(ra[0].x, ra[0].y), packh2(ra[0].z, ra[0].w),
                packh2(ra[1].x, ra[1].y), packh2(ra[1].z, ra[1].w));
            *(uint4*)&As[arow][acol + 8] = make_uint4(
                packh2(ra[2].x, ra[2].y), packh2(ra[2].z, ra[2].w),
                packh2(ra[3].x, ra[3].y), packh2(ra[3].z, ra[3].w));
        }
        *(uint4*)&Bs[brow][bcol] = make_uint4(
            packh2(rb[0].x, rb[0].y), packh2(rb[0].z, rb[0].w),
            packh2(rb[1].x, rb[1].y), packh2(rb[1].z, rb[1].w));
        *(uint4*)&Bs[brow][bcol + 8] = make_uint4(
            packh2(rb[2].x, rb[2].y), packh2(rb[2].z, rb[2].w),
            packh2(rb[3].x, rb[3].y), packh2(rb[3].z, rb[3].w));
        __syncthreads();

        const int kn = k0 + 32;
        if (kn < 1024) {
            if (AHALF) {
                ra16[0] = ((const uint4*)(Ah + a_off + kn))[0];
                ra16[1] = ((const uint4*)(Ah + a_off + kn))[1];
            } else {
#pragma unroll
                for (int i = 0; i < 4; i++) ra[i] = *(const float4*)(Af + a_off + kn + i * 4);
            }
#pragma unroll
            for (int i = 0; i < 4; i++) rb[i] = *(const float4*)(Wg + (size_t)kn * NG + i * 4);
        }

#pragma unroll
        for (int kk = 0; kk < 32; kk += 16) {
            wmma::fragment<wmma::matrix_a, 16, 16, 16, __half, wmma::row_major> fa[4];
            wmma::fragment<wmma::matrix_b, 16, 16, 16, __half, wmma::row_major> fb[2];
#pragma unroll
            for (int i = 0; i < 4; i++)
                wmma::load_matrix_sync(fa[i], &As[wm * 64 + i * 16][kk], 40);
#pragma unroll
            for (int j = 0; j < 2; j++)
                wmma::load_matrix_sync(fb[j], &Bs[kk][wn * 32 + j * 16], 136);
#pragma unroll
            for (int i = 0; i < 4; i++)
#pragma unroll
                for (int j = 0; j < 2; j++)
                    wmma::mma_sync(acc[i][j], fa[i], fb[j], acc[i][j]);
        }
    }

    float* base = CT + (size_t)bm * NG * 128;
#pragma unroll
    for (int i = 0; i < 4; i++)
#pragma unroll
        for (int j = 0; j < 2; j++) {
            const int col = bn * 128 + wn * 32 + j * 16;
            const int b   = wm * 64 + i * 16;
            wmma::store_matrix_sync(base + (size_t)col * 128 + b, acc[i][j],
                                    128, wmma::mem_col_major);
        }
}

// =================================================================================
__global__ void lstm_init()
{
    const int i = blockIdx.x * blockDim.x + threadIdx.x;   // 65536
    if (i == 0) g_count = 0;
    ((uint32_t*)g_h16[0])[i] = 0u;
}

// =================================================================================
// Persistent fp16 HMMA recurrence. 128 CTAs x 256 threads (4 mquad x 2 khalf).
// NEW vs R9: fp16 accumulators per K=128 chunk (2x HMMA rate), promoted
// elementwise into fp32 accumulator fragments after each chunk.
// =================================================================================
__global__ void __launch_bounds__(THR_R, 1) lstm_recur(
    const float* __restrict__ Whh,      // [HID, NG]
    const float* __restrict__ gatesT,   // [T][col][b]
    const float* __restrict__ b1, const float* __restrict__ b2,
    __half* __restrict__ seq16,         // layer-0 output (or null)
    float*  __restrict__ seq32,         // last-layer output (or null)
    float* __restrict__ hT, float* __restrict__ cT)
{
    extern __shared__ __align__(16) char smem[];
    __half* Ws   = (__half*)(smem + SM_W);       // [1024][40]
    float*  Gs0  = (float*) (smem + SM_G);       // [128][40]
    float*  Gs1  = Gs0 + 128 * 40;
    float*  bias = (float*) (smem + SM_BIAS);    // [32]
    const uint32_t sbase = smem_u32(smem);

    const int tid   = threadIdx.x;
    const int wid   = tid >> 5;
    const int mquad = wid & 3;          // rows mquad*32..+32
    const int khalf = wid >> 2;         // 0: kk<64 of chunk, 1: kk>=64
    const int bx  = blockIdx.x;
    const int j0  = bx * 8;

    // ---- stage W slice (fp16) + bias, once ----
    for (int idx = tid; idx < 1024 * 32; idx += THR_R) {
        const int k = idx >> 5, n = idx & 31;
        const int gate = n & 3, jl = n >> 2;
        Ws[k * 40 + n] = __float2half_rn(Whh[(size_t)k * NG + gate * HID + j0 + jl]);
    }
    if (tid < 32) {
        const int gate = tid & 3, jl = tid >> 2;
        bias[tid] = b1[gate * HID + j0 + jl] + b2[gate * HID + j0 + jl];
    }
    __syncthreads();

    // cell mapping
    const int m     = tid & 127;
    const int nhalf = tid >> 7;
    float c4[4];
#pragma unroll
    for (int q = 0; q < 4; q++) c4[q] = 0.f;

    // gt prefetch for t = 0
    float gt[16];
    {
        const float* gb = gatesT + m;
#pragma unroll
        for (int q = 0; q < 4; q++)
#pragma unroll
            for (int g = 0; g < 4; g++)
                gt[q * 4 + g] = gb[(size_t)(g * HID + j0 + nhalf * 4 + q) * BATCH];
    }

    for (int t = 0; t < TSTEPS; ++t) {
        // ---- wait for generation t ----
        if (t > 0) {
            if (tid == 0) {
                const unsigned target = (unsigned)t * NCTA_R;
                while (acq_ld(&g_count) < target) { }
            }
            __syncthreads();
        }

        const __half* hin  = g_h16[t & 1];
        __half*       hout = g_h16[(t + 1) & 1];

        // fp32 running totals (fragment layout)
        wmma::fragment<wmma::accumulator, 16, 16, 16, float> accf[2][2];
#pragma unroll
        for (int i = 0; i < 2; i++)
#pragma unroll
            for (int j = 0; j < 2; j++) wmma::fill_fragment(accf[i][j], 0.f);

        // ---- stage chunks 0,1 (depth-2) ----
#pragma unroll
        for (int c = 0; c < 2; ++c) {
            const uint32_t dbase = sbase + SM_A + c * SM_ABUF;
            const __half* hp = hin + c * 128;
#pragma unroll
            for (int u = 0; u < 8; u++) {
                const int idx = u * THR_R + tid;
                const int row = idx >> 4, k8 = (idx & 15) * 8;
                cp16(dbase + (uint32_t)(row * 136 + k8) * 2,
                     hp + (size_t)row * HID + k8);
            }
            CP_COMMIT();
        }

        // ---- 8 chunks, 3 buffers, 1 sync per chunk; fp16 accum per chunk ----
#pragma unroll 1
        for (int cc = 0; cc < 8; ++cc) {
            if (cc < 7) CP_WAIT1(); else CP_WAIT0();
            __syncthreads();

            if (cc < 6) {
                const int cn = cc + 2;
                const uint32_t dbase = sbase + SM_A + (cn % 3) * SM_ABUF;
                const __half* hp = hin + cn * 128;
#pragma unroll
                for (int u = 0; u < 8; u++) {
                    const int idx = u * THR_R + tid;
                    const int row = idx >> 4, k8 = (idx & 15) * 8;
                    cp16(dbase + (uint32_t)(row * 136 + k8) * 2,
                         hp + (size_t)row * HID + k8);
                }
                CP_COMMIT();
            }

            wmma::fragment<wmma::accumulator, 16, 16, 16, __half> acch[2][2];
#pragma unroll
            for (int i = 0; i < 2; i++)
#pragma unroll
                for (int j = 0; j < 2; j++)
                    wmma::fill_fragment(acch[i][j], __float2half(0.f));

            const __half* Ap = (const __half*)(smem + SM_A + (cc % 3) * SM_ABUF)
                             + (size_t)mquad * 32 * 136 + khalf * 64;
            const __half* Wp = Ws + (size_t)(cc * 128 + khalf * 64) * 40;
#pragma unroll
            for (int kk = 0; kk < 64; kk += 16) {
                wmma::fragment<wmma::matrix_a, 16, 16, 16, __half, wmma::row_major> fa[2];
                wmma::fragment<wmma::matrix_b, 16, 16, 16, __half, wmma::row_major> fb[2];
#pragma unroll
                for (int i = 0; i < 2; i++)
                    wmma::load_matrix_sync(fa[i], Ap + (size_t)(i * 16) * 136 + kk, 136);
#pragma unroll
                for (int j = 0; j < 2; j++)
                    wmma::load_matrix_sync(fb[j], Wp + (size_t)kk * 40 + j * 16, 40);
#pragma unroll
                for (int i = 0; i < 2; i++)
#pragma unroll
                    for (int j = 0; j < 2; j++)
                        wmma::mma_sync(acch[i][j], fa[i], fb[j], acch[i][j]);
            }

            // promote chunk fp16 accum into fp32 totals (same de-facto layout)
#pragma unroll
            for (int i = 0; i < 2; i++)
#pragma unroll
                for (int j = 0; j < 2; j++)
#pragma unroll
                    for (int e = 0; e < accf[i][j].num_elements; e++)
                        accf[i][j].x[e] += __half2float(acch[i][j].x[e]);
        }

        // ---- partial gate tiles ----
        float* Gsw = khalf ? Gs1 : Gs0;
#pragma unroll
        for (int i = 0; i < 2; i++)
#pragma unroll
            for (int j = 0; j < 2; j++)
                wmma::store_matrix_sync(Gsw + (size_t)(mquad * 32 + i * 16) * 40 + j * 16,
                                        accf[i][j], 40, wmma::mem_row_major);
        __syncthreads();

        // ---- LSTM cell ----
        float hn[4];
#pragma unroll
        for (int q = 0; q < 4; q++) {
            const int n = nhalf * 16 + q * 4;
            const float4 v0 = *(const float4*)(Gs0 + (size_t)m * 40 + n);
            const float4 v1 = *(const float4*)(Gs1 + (size_t)m * 40 + n);
            const float zi = v0.x + v1.x + gt[q * 4 + 0] + bias[n + 0];
            const float zf = v0.y + v1.y + gt[q * 4 + 1] + bias[n + 1];
            const float zg = v0.z + v1.z + gt[q * 4 + 2] + bias[n + 2];
            const float zo = v0.w + v1.w + gt[q * 4 + 3] + bias[n + 3];
            const float cn = sigf(zf) * c4[q] + sigf(zi) * tanhf(zg);
            hn[q] = sigf(zo) * tanhf(cn);
            c4[q] = cn;
        }

        // ---- publish h, arrive ----
        const size_t ob = (size_t)m * HID + j0 + nhalf * 4;
        const uint2 upk = make_uint2(packh2(hn[0], hn[1]), packh2(hn[2], hn[3]));
        *(uint2*)(hout + ob) = upk;

        __syncthreads();
        if (tid == 0) rel_add1(&g_count);

        // ---- work shadow ----
        if (seq16) *(uint2*)(seq16 + (size_t)t * BATCH * HID + ob) = upk;
        if (seq32)
            *(float4*)(seq32 + (size_t)t * BATCH * HID + ob) =
                make_float4(hn[0], hn[1], hn[2], hn[3]);
        if (t == TSTEPS - 1) {
            *(float4*)(hT + ob) = make_float4(hn[0], hn[1], hn[2], hn[3]);
            *(float4*)(cT + ob) = make_float4(c4[0], c4[1], c4[2], c4[3]);
        }
        if (t + 1 < TSTEPS) {
            const float* gb = gatesT + (size_t)(t + 1) * NG * BATCH + m;
#pragma unroll
            for (int q = 0; q < 4; q++)
#pragma unroll
                for (int g = 0; g < 4; g++)
                    gt[q * 4 + g] = gb[(size_t)(g * HID + j0 + nhalf * 4 + q) * BATCH];
        }
    }
}

// =================================================================================
extern "C" void kernel_launch(void* const* d_in, const int* in_sizes, int n_in,
                              void* d_out, int out_size)
{
    const float* x   = (const float*)d_in[0];
    const float* wih = (const float*)d_in[1];
    const float* whh = (const float*)d_in[2];
    const float* bih = (const float*)d_in[3];
    const float* bhh = (const float*)d_in[4];
    float* out = (float*)d_out;

    cudaFuncSetAttribute(lstm_recur, cudaFuncAttributeMaxDynamicSharedMemorySize, SM_TOTAL);

    float  *gatesT;
    __half *hseq16;
    cudaGetSymbolAddress((void**)&gatesT, g_gatesT);
    cudaGetSymbolAddress((void**)&hseq16, g_hseq16);

    float* hT_base = out + (size_t)TSTEPS * BATCH * HID;
    float* cT_base = hT_base + (size_t)NLAYER * BATCH * HID;

    for (int l = 0; l < NLAYER; ++l) {
        const float* Wih = wih + (size_t)l * 1024 * NG;
        const float* Whh = whh + (size_t)l * HID * NG;
        const float* B1  = bih + (size_t)l * NG;
        const float* B2  = bhh + (size_t)l * NG;
        float* hT = hT_base + (size_t)l * BATCH * HID;
        float* cT = cT_base + (size_t)l * BATCH * HID;

        if (l == 0)
            gemm_input<false><<<dim3(NG / 128, TSTEPS), 256>>>(x, Wih, gatesT);
        else
            gemm_input<true ><<<dim3(NG / 128, TSTEPS), 256>>>(hseq16, Wih, gatesT);

        lstm_init<<<256, 256>>>();

        lstm_recur<<<NCTA_R, THR_R, SM_TOTAL>>>(
            Whh, gatesT, B1, B2,
            (l == 0) ? hseq16 : (__half*)nullptr,
            (l == 1) ? out    : (float*)nullptr,
            hT, cT);
    }
}

// round 11
// speedup vs baseline: 1.1345x; 1.1345x over previous
#include <cuda_runtime.h>
#include <cuda_fp16.h>
#include <mma.h>
#include <cstdint>

using namespace nvcuda;

#define TSTEPS 512
#define BATCH  128
#define HID    1024
#define NG     4096
#define NLAYER 2
#define NCTA_R 128
#define THR_TOT 320   // 8 consumer warps + 2 producer warps
#define N_CONS  256

// ---------------- device scratch ----------------
__device__ float  g_gatesT[(size_t)TSTEPS * NG * BATCH];          // [t][col][b]
__device__ __align__(16) __half g_hseq16[(size_t)TSTEPS * BATCH * HID];
__device__ __align__(16) __half g_h16[2][BATCH * HID];            // ping-pong h
__device__ unsigned int g_count;

// ---------------- recurrence smem layout (bytes) ----------------
// W: 1024 x 40 half = 81920 ; A: 3 x (128 x 136 half) = 104448 ;
// G: 2 x (128 x 40 float) = 40960 ; bias 256   -> 227584 (fits, same as R9)
#define SM_W     0
#define SM_A     81920
#define SM_ABUF  34816
#define SM_G     186368
#define SM_BIAS  227328
#define SM_TOTAL 227584

__device__ __forceinline__ uint32_t smem_u32(const void* p) {
    uint32_t a;
    asm("{ .reg .u64 t; cvta.to.shared.u64 t, %1; cvt.u32.u64 %0, t; }" : "=r"(a) : "l"(p));
    return a;
}
__device__ __forceinline__ void cp16(uint32_t dst, const void* src) {
    asm volatile("cp.async.cg.shared.global [%0], [%1], 16;" :: "r"(dst), "l"(src));
}
#define CP_COMMIT() asm volatile("cp.async.commit_group;" ::: "memory")
#define CP_WAIT1()  asm volatile("cp.async.wait_group 1;" ::: "memory")
#define CP_WAIT0()  asm volatile("cp.async.wait_group 0;" ::: "memory")

#define BAR_SYNC(id, n)   asm volatile("bar.sync %0, %1;"   :: "r"(id), "r"(n) : "memory")
#define BAR_ARRIVE(id, n) asm volatile("bar.arrive %0, %1;" :: "r"(id), "r"(n) : "memory")

__device__ __forceinline__ void rel_add1(unsigned int* p) {
    asm volatile("red.release.gpu.global.add.u32 [%0], 1;" :: "l"(p) : "memory");
}
__device__ __forceinline__ unsigned int acq_ld(const unsigned int* p) {
    unsigned int v;
    asm volatile("ld.acquire.gpu.global.u32 %0, [%1];" : "=r"(v) : "l"(p) : "memory");
    return v;
}

__device__ __forceinline__ float sigf(float x) { return 1.f / (1.f + __expf(-x)); }
__device__ __forceinline__ uint32_t packh2(float a, float b) {
    return (uint32_t)__half_as_ushort(__float2half_rn(a)) |
           ((uint32_t)__half_as_ushort(__float2half_rn(b)) << 16);
}

// =================================================================================
// Input GEMM (unchanged — controlled experiment on the recurrence)
// =================================================================================
template<bool AHALF>
__global__ void __launch_bounds__(256) gemm_input(const void* __restrict__ Av,
                                                  const float* __restrict__ W,
                                                  float* __restrict__ CT)
{
    __shared__ __half As[128][40];
    __shared__ __half Bs[32][136];

    const int tid  = threadIdx.x;
    const int warp = tid >> 5;
    const int wm = warp >> 2;
    const int wn = warp & 3;
    const int bm = blockIdx.y;
    const int bn = blockIdx.x;

    const int arow = tid >> 1, acol = (tid & 1) * 16;
    const int brow = tid >> 3, bcol = (tid & 7) * 16;

    const float*  Af = (const float*) Av;
    const __half* Ah = (const __half*)Av;
    const size_t  a_off = (size_t)(bm * 128 + arow) * 1024 + acol;
    const float*  Wg = W + (size_t)brow * NG + bn * 128 + bcol;

    wmma::fragment<wmma::accumulator, 16, 16, 16, float> acc[4][2];
#pragma unroll
    for (int i = 0; i < 4; i++)
#pragma unroll
        for (int j = 0; j < 2; j++) wmma::fill_fragment(acc[i][j], 0.f);

    float4 ra[4]; uint4 ra16[2]; float4 rb[4];
    if (AHALF) {
        ra16[0] = ((const uint4*)(Ah + a_off))[0];
        ra16[1] = ((const uint4*)(Ah + a_off))[1];
    } else {
#pragma unroll
        for (int i = 0; i < 4; i++) ra[i] = *(const float4*)(Af + a_off + i * 4);
    }
#pragma unroll
    for (int i = 0; i < 4; i++) rb[i] = *(const float4*)(Wg + i * 4);

    for (int k0 = 0; k0 < 1024; k0 += 32) {
        __syncthreads();
        if (AHALF) {
            *(uint4*)&As[arow][acol]     = ra16[0];
            *(uint4*)&As[arow][acol + 8] = ra16[1];
        } else {
            *(uint4*)&As[arow][acol] = make_uint4(
                packh2(ra[0].x, ra[0].y), packh2(ra[0].z, ra[0].w),
                packh2(ra[1].x, ra[1].y), packh2(ra[1].z, ra[1].w));
            *(uint4*)&As[arow][acol + 8] = make_uint4(
                packh2(ra[2].x, ra[2].y), packh2(ra[2].z, ra[2].w),
                packh2(ra[3].x, ra[3].y), packh2(ra[3].z, ra[3].w));
        }
        *(uint4*)&Bs[brow][bcol] = make_uint4(
            packh2(rb[0].x, rb[0].y), packh2(rb[0].z, rb[0].w),
            packh2(rb[1].x, rb[1].y), packh2(rb[1].z, rb[1].w));
        *(uint4*)&Bs[brow][bcol + 8] = make_uint4(
            packh2(rb[2].x, rb[2].y), packh2(rb[2].z, rb[2].w),
            packh2(rb[3].x, rb[3].y), packh2(rb[3].z, rb[3].w));
        __syncthreads();

        const int kn = k0 + 32;
        if (kn < 1024) {
            if (AHALF) {
                ra16[0] = ((const uint4*)(Ah + a_off + kn))[0];
                ra16[1] = ((const uint4*)(Ah + a_off + kn))[1];
            } else {
#pragma unroll
                for (int i = 0; i < 4; i++) ra[i] = *(const float4*)(Af + a_off + kn + i * 4);
            }
#pragma unroll
            for (int i = 0; i < 4; i++) rb[i] = *(const float4*)(Wg + (size_t)kn * NG + i * 4);
        }

#pragma unroll
        for (int kk = 0; kk < 32; kk += 16) {
            wmma::fragment<wmma::matrix_a, 16, 16, 16, __half, wmma::row_major> fa[4];
            wmma::fragment<wmma::matrix_b, 16, 16, 16, __half, wmma::row_major> fb[2];
#pragma unroll
            for (int i = 0; i < 4; i++)
                wmma::load_matrix_sync(fa[i], &As[wm * 64 + i * 16][kk], 40);
#pragma unroll
            for (int j = 0; j < 2; j++)
                wmma::load_matrix_sync(fb[j], &Bs[kk][wn * 32 + j * 16], 136);
#pragma unroll
            for (int i = 0; i < 4; i++)
#pragma unroll
                for (int j = 0; j < 2; j++)
                    wmma::mma_sync(acc[i][j], fa[i], fb[j], acc[i][j]);
        }
    }

    float* base = CT + (size_t)bm * NG * 128;
#pragma unroll
    for (int i = 0; i < 4; i++)
#pragma unroll
        for (int j = 0; j < 2; j++) {
            const int col = bn * 128 + wn * 32 + j * 16;
            const int b   = wm * 64 + i * 16;
            wmma::store_matrix_sync(base + (size_t)col * 128 + b, acc[i][j],
                                    128, wmma::mem_col_major);
        }
}

// =================================================================================
__global__ void lstm_init()
{
    const int i = blockIdx.x * blockDim.x + threadIdx.x;   // 65536
    if (i == 0) g_count = 0;
    ((uint32_t*)g_h16[0])[i] = 0u;
}

// =================================================================================
// Persistent fp16 HMMA recurrence, WARP-SPECIALIZED.
// 128 CTAs x 320 threads: warps 0-7 consumers (GEMM M32-strips x K-halves + cell),
// warps 8-9 producers (cp.async h staging + generation polling).
// 3 slot buffers; named barriers: FULL(s)=1+s, EMPTY(s)=4+s (count 320),
// consumer-only barrier id 9 (count 256). slot = (t*8+cc) % 3.
// =================================================================================
__global__ void __launch_bounds__(THR_TOT, 1) lstm_recur(
    const float* __restrict__ Whh,      // [HID, NG]
    const float* __restrict__ gatesT,   // [T][col][b]
    const float* __restrict__ b1, const float* __restrict__ b2,
    __half* __restrict__ seq16,         // layer-0 output (or null)
    float*  __restrict__ seq32,         // last-layer output (or null)
    float* __restrict__ hT, float* __restrict__ cT)
{
    extern __shared__ __align__(16) char smem[];
    __half* Ws   = (__half*)(smem + SM_W);       // [1024][40]
    float*  Gs0  = (float*) (smem + SM_G);       // [128][40]
    float*  Gs1  = Gs0 + 128 * 40;
    float*  bias = (float*) (smem + SM_BIAS);    // [32]
    const uint32_t sbase = smem_u32(smem);

    const int tid = threadIdx.x;
    const int bx  = blockIdx.x;
    const int j0  = bx * 8;

    // ---- stage W slice (fp16) + bias once, with ALL 320 threads ----
    for (int idx = tid; idx < 1024 * 32; idx += THR_TOT) {
        const int k = idx >> 5, n = idx & 31;
        const int gate = n & 3, jl = n >> 2;
        Ws[k * 40 + n] = __float2half_rn(Whh[(size_t)k * NG + gate * HID + j0 + jl]);
    }
    if (tid < 32) {
        const int gate = tid & 3, jl = tid >> 2;
        bias[tid] = b1[gate * HID + j0 + jl] + b2[gate * HID + j0 + jl];
    }
    __syncthreads();   // only block-wide sync; roles diverge below

    if (tid >= N_CONS) {
        // =========================== PRODUCER WARPS ===========================
        const int ptid = tid - N_CONS;   // 0..63
#pragma unroll 1
        for (int t = 0; t < TSTEPS; ++t) {
            if (t > 0) {
                const unsigned target = (unsigned)t * NCTA_R;
                while (acq_ld(&g_count) < target) { }
            }
            const __half* hin = g_h16[t & 1];
            const int base = t * 8;
#pragma unroll 1
            for (int cc = 0; cc < 8; ++cc) {
                const int g = base + cc;
                const int slot = g % 3;
                if (g >= 3) BAR_SYNC(4 + slot, THR_TOT);   // wait slot empty
                const uint32_t dbase = sbase + SM_A + slot * SM_ABUF;
                const __half* hp = hin + cc * 128;
#pragma unroll
                for (int u = 0; u < 32; u++) {
                    const int idx = u * 64 + ptid;
                    const int row = idx >> 4, k8 = (idx & 15) * 8;
                    cp16(dbase + (uint32_t)(row * 136 + k8) * 2,
                         hp + (size_t)row * HID + k8);
                }
                CP_COMMIT();
                if (cc >= 1) {
                    CP_WAIT1();                             // chunk cc-1 arrived
                    BAR_ARRIVE(1 + ((g - 1) % 3), THR_TOT); // announce full
                }
            }
            CP_WAIT0();                                     // last chunk arrived
            BAR_ARRIVE(1 + ((base + 7) % 3), THR_TOT);
        }
        return;
    }

    // ============================ CONSUMER WARPS ============================
    const int wid   = tid >> 5;
    const int mquad = wid & 3;          // rows mquad*32..+32
    const int khalf = wid >> 2;         // 0: kk<64 of chunk, 1: kk>=64

    const int m     = tid & 127;
    const int nhalf = tid >> 7;
    float c4[4];
#pragma unroll
    for (int q = 0; q < 4; q++) c4[q] = 0.f;

    // gt prefetch for t = 0
    float gt[16];
    {
        const float* gb = gatesT + m;
#pragma unroll
        for (int q = 0; q < 4; q++)
#pragma unroll
            for (int g = 0; g < 4; g++)
                gt[q * 4 + g] = gb[(size_t)(g * HID + j0 + nhalf * 4 + q) * BATCH];
    }

#pragma unroll 1
    for (int t = 0; t < TSTEPS; ++t) {
        __half* hout = g_h16[(t + 1) & 1];

        wmma::fragment<wmma::accumulator, 16, 16, 16, float> acc[2][2];
#pragma unroll
        for (int i = 0; i < 2; i++)
#pragma unroll
            for (int j = 0; j < 2; j++) wmma::fill_fragment(acc[i][j], 0.f);

        // ---- 8 chunks, gated on producer-filled slots ----
#pragma unroll 1
        for (int cc = 0; cc < 8; ++cc) {
            const int slot = (t * 8 + cc) % 3;
            BAR_SYNC(1 + slot, THR_TOT);    // wait slot full

            const __half* Ap = (const __half*)(smem + SM_A + slot * SM_ABUF)
                             + (size_t)mquad * 32 * 136 + khalf * 64;
            const __half* Wp = Ws + (size_t)(cc * 128 + khalf * 64) * 40;
#pragma unroll
            for (int kk = 0; kk < 64; kk += 16) {
                wmma::fragment<wmma::matrix_a, 16, 16, 16, __half, wmma::row_major> fa[2];
                wmma::fragment<wmma::matrix_b, 16, 16, 16, __half, wmma::row_major> fb[2];
#pragma unroll
                for (int i = 0; i < 2; i++)
                    wmma::load_matrix_sync(fa[i], Ap + (size_t)(i * 16) * 136 + kk, 136);
#pragma unroll
                for (int j = 0; j < 2; j++)
                    wmma::load_matrix_sync(fb[j], Wp + (size_t)kk * 40 + j * 16, 40);
#pragma unroll
                for (int i = 0; i < 2; i++)
#pragma unroll
                    for (int j = 0; j < 2; j++)
                        wmma::mma_sync(acc[i][j], fa[i], fb[j], acc[i][j]);
            }
            BAR_ARRIVE(4 + slot, THR_TOT);  // slot consumed
        }

        // ---- partial gate tiles ----
        float* Gsw = khalf ? Gs1 : Gs0;
#pragma unroll
        for (int i = 0; i < 2; i++)
#pragma unroll
            for (int j = 0; j < 2; j++)
                wmma::store_matrix_sync(Gsw + (size_t)(mquad * 32 + i * 16) * 40 + j * 16,
                                        acc[i][j], 40, wmma::mem_row_major);
        BAR_SYNC(9, N_CONS);

        // ---- LSTM cell ----
        float hn[4];
#pragma unroll
        for (int q = 0; q < 4; q++) {
            const int n = nhalf * 16 + q * 4;
            const float4 v0 = *(const float4*)(Gs0 + (size_t)m * 40 + n);
            const float4 v1 = *(const float4*)(Gs1 + (size_t)m * 40 + n);
            const float zi = v0.x + v1.x + gt[q * 4 + 0] + bias[n + 0];
            const float zf = v0.y + v1.y + gt[q * 4 + 1] + bias[n + 1];
            const float zg = v0.z + v1.z + gt[q * 4 + 2] + bias[n + 2];
            const float zo = v0.w + v1.w + gt[q * 4 + 3] + bias[n + 3];
            const float cn = sigf(zf) * c4[q] + sigf(zi) * tanhf(zg);
            hn[q] = sigf(zo) * tanhf(cn);
            c4[q] = cn;
        }

        // ---- publish h, arrive ----
        const size_t ob = (size_t)m * HID + j0 + nhalf * 4;
        const uint2 upk = make_uint2(packh2(hn[0], hn[1]), packh2(hn[2], hn[3]));
        *(uint2*)(hout + ob) = upk;

        BAR_SYNC(9, N_CONS);               // all consumer hout stores done
        if (tid == 0) rel_add1(&g_count);  // release-arrive

        // ---- work shadow ----
        if (seq16) *(uint2*)(seq16 + (size_t)t * BATCH * HID + ob) = upk;
        if (seq32)
            *(float4*)(seq32 + (size_t)t * BATCH * HID + ob) =
                make_float4(hn[0], hn[1], hn[2], hn[3]);
        if (t == TSTEPS - 1) {
            *(float4*)(hT + ob) = make_float4(hn[0], hn[1], hn[2], hn[3]);
            *(float4*)(cT + ob) = make_float4(c4[0], c4[1], c4[2], c4[3]);
        }
        if (t + 1 < TSTEPS) {
            const float* gb = gatesT + (size_t)(t + 1) * NG * BATCH + m;
#pragma unroll
            for (int q = 0; q < 4; q++)
#pragma unroll
                for (int g = 0; g < 4; g++)
                    gt[q * 4 + g] = gb[(size_t)(g * HID + j0 + nhalf * 4 + q) * BATCH];
        }
    }
}

// =================================================================================
extern "C" void kernel_launch(void* const* d_in, const int* in_sizes, int n_in,
                              void* d_out, int out_size)
{
    const float* x   = (const float*)d_in[0];
    const float* wih = (const float*)d_in[1];
    const float* whh = (const float*)d_in[2];
    const float* bih = (const float*)d_in[3];
    const float* bhh = (const float*)d_in[4];
    float* out = (float*)d_out;

    cudaFuncSetAttribute(lstm_recur, cudaFuncAttributeMaxDynamicSharedMemorySize, SM_TOTAL);

    float  *gatesT;
    __half *hseq16;
    cudaGetSymbolAddress((void**)&gatesT, g_gatesT);
    cudaGetSymbolAddress((void**)&hseq16, g_hseq16);

    float* hT_base = out + (size_t)TSTEPS * BATCH * HID;
    float* cT_base = hT_base + (size_t)NLAYER * BATCH * HID;

    for (int l = 0; l < NLAYER; ++l) {
        const float* Wih = wih + (size_t)l * 1024 * NG;
        const float* Whh = whh + (size_t)l * HID * NG;
        const float* B1  = bih + (size_t)l * NG;
        const float* B2  = bhh + (size_t)l * NG;
        float* hT = hT_base + (size_t)l * BATCH * HID;
        float* cT = cT_base + (size_t)l * BATCH * HID;

        if (l == 0)
            gemm_input<false><<<dim3(NG / 128, TSTEPS), 256>>>(x, Wih, gatesT);
        else
            gemm_input<true ><<<dim3(NG / 128, TSTEPS), 256>>>(hseq16, Wih, gatesT);

        lstm_init<<<256, 256>>>();

        lstm_recur<<<NCTA_R, THR_TOT, SM_TOTAL>>>(
            Whh, gatesT, B1, B2,
            (l == 0) ? hseq16 : (__half*)nullptr,
            (l == 1) ? out    : (float*)nullptr,
            hT, cT);
    }
}

// round 12
// speedup vs baseline: 1.1460x; 1.0102x over previous
#include <cuda_runtime.h>
#include <cuda_fp16.h>
#include <mma.h>
#include <cstdint>

using namespace nvcuda;

#define TSTEPS 512
#define BATCH  128
#define HID    1024
#define NG     4096
#define NLAYER 2
#define NCTA_R 128
#define THR_TOT 320   // 8 consumer warps + 2 producer warps
#define N_CONS  256

// ---------------- device scratch ----------------
__device__ float  g_gatesT[(size_t)TSTEPS * NG * BATCH];          // [t][col][b]
__device__ __align__(16) __half g_hseq16[(size_t)TSTEPS * BATCH * HID];
__device__ __align__(16) __half g_h16[2][BATCH * HID];            // ping-pong h
__device__ unsigned int g_count;

// ---------------- recurrence smem layout (bytes) ----------------
// W: 1024 x 72 half = 147456 ; A: 2 x (64 x 136 half) = 34816 ;
// G: 2 x (64 x 68 float) = 34816 ; bias 256  -> 217344
#define SM_W     0
#define SM_A     147456
#define SM_ABUF  17408
#define SM_G     182272
#define SM_BIAS  217088
#define SM_TOTAL 217344

__device__ __forceinline__ uint32_t smem_u32(const void* p) {
    uint32_t a;
    asm("{ .reg .u64 t; cvta.to.shared.u64 t, %1; cvt.u32.u64 %0, t; }" : "=r"(a) : "l"(p));
    return a;
}
__device__ __forceinline__ void cp16(uint32_t dst, const void* src) {
    asm volatile("cp.async.cg.shared.global [%0], [%1], 16;" :: "r"(dst), "l"(src));
}
#define CP_COMMIT() asm volatile("cp.async.commit_group;" ::: "memory")
#define CP_WAIT1()  asm volatile("cp.async.wait_group 1;" ::: "memory")
#define CP_WAIT0()  asm volatile("cp.async.wait_group 0;" ::: "memory")

#define BAR_SYNC(id, n)   asm volatile("bar.sync %0, %1;"   :: "r"(id), "r"(n) : "memory")
#define BAR_ARRIVE(id, n) asm volatile("bar.arrive %0, %1;" :: "r"(id), "r"(n) : "memory")

__device__ __forceinline__ void rel_add1(unsigned int* p) {
    asm volatile("red.release.gpu.global.add.u32 [%0], 1;" :: "l"(p) : "memory");
}
__device__ __forceinline__ unsigned int acq_ld(const unsigned int* p) {
    unsigned int v;
    asm volatile("ld.acquire.gpu.global.u32 %0, [%1];" : "=r"(v) : "l"(p) : "memory");
    return v;
}

__device__ __forceinline__ float sigf(float x) { return 1.f / (1.f + __expf(-x)); }
__device__ __forceinline__ uint32_t packh2(float a, float b) {
    return (uint32_t)__half_as_ushort(__float2half_rn(a)) |
           ((uint32_t)__half_as_ushort(__float2half_rn(b)) << 16);
}

// =================================================================================
// Input GEMM (unchanged)
// =================================================================================
template<bool AHALF>
__global__ void __launch_bounds__(256) gemm_input(const void* __restrict__ Av,
                                                  const float* __restrict__ W,
                                                  float* __restrict__ CT)
{
    __shared__ __half As[128][40];
    __shared__ __half Bs[32][136];

    const int tid  = threadIdx.x;
    const int warp = tid >> 5;
    const int wm = warp >> 2;
    const int wn = warp & 3;
    const int bm = blockIdx.y;
    const int bn = blockIdx.x;

    const int arow = tid >> 1, acol = (tid & 1) * 16;
    const int brow = tid >> 3, bcol = (tid & 7) * 16;

    const float*  Af = (const float*) Av;
    const __half* Ah = (const __half*)Av;
    const size_t  a_off = (size_t)(bm * 128 + arow) * 1024 + acol;
    const float*  Wg = W + (size_t)brow * NG + bn * 128 + bcol;

    wmma::fragment<wmma::accumulator, 16, 16, 16, float> acc[4][2];
#pragma unroll
    for (int i = 0; i < 4; i++)
#pragma unroll
        for (int j = 0; j < 2; j++) wmma::fill_fragment(acc[i][j], 0.f);

    float4 ra[4]; uint4 ra16[2]; float4 rb[4];
    if (AHALF) {
        ra16[0] = ((const uint4*)(Ah + a_off))[0];
        ra16[1] = ((const uint4*)(Ah + a_off))[1];
    } else {
#pragma unroll
        for (int i = 0; i < 4; i++) ra[i] = *(const float4*)(Af + a_off + i * 4);
    }
#pragma unroll
    for (int i = 0; i < 4; i++) rb[i] = *(const float4*)(Wg + i * 4);

    for (int k0 = 0; k0 < 1024; k0 += 32) {
        __syncthreads();
        if (AHALF) {
            *(uint4*)&As[arow][acol]     = ra16[0];
            *(uint4*)&As[arow][acol + 8] = ra16[1];
        } else {
            *(uint4*)&As[arow][acol] = make_uint4(
                packh2(ra[0].x, ra[0].y), packh2(ra[0].z, ra[0].w),
                packh2(ra[1].x, ra[1].y), packh2(ra[1].z, ra[1].w));
            *(uint4*)&As[arow][acol + 8] = make_uint4(
                packh2(ra[2].x, ra[2].y), packh2(ra[2].z, ra[2].w),
                packh2(ra[3].x, ra[3].y), packh2(ra[3].z, ra[3].w));
        }
        *(uint4*)&Bs[brow][bcol] = make_uint4(
            packh2(rb[0].x, rb[0].y), packh2(rb[0].z, rb[0].w),
            packh2(rb[1].x, rb[1].y), packh2(rb[1].z, rb[1].w));
        *(uint4*)&Bs[brow][bcol + 8] = make_uint4(
            packh2(rb[2].x, rb[2].y), packh2(rb[2].z, rb[2].w),
            packh2(rb[3].x, rb[3].y), packh2(rb[3].z, rb[3].w));
        __syncthreads();

        const int kn = k0 + 32;
        if (kn < 1024) {
            if (AHALF) {
                ra16[0] = ((const uint4*)(Ah + a_off + kn))[0];
                ra16[1] = ((const uint4*)(Ah + a_off + kn))[1];
            } else {
#pragma unroll
                for (int i = 0; i < 4; i++) ra[i] = *(const float4*)(Af + a_off + kn + i * 4);
            }
#pragma unroll
            for (int i = 0; i < 4; i++) rb[i] = *(const float4*)(Wg + (size_t)kn * NG + i * 4);
        }

#pragma unroll
        for (int kk = 0; kk < 32; kk += 16) {
            wmma::fragment<wmma::matrix_a, 16, 16, 16, __half, wmma::row_major> fa[4];
            wmma::fragment<wmma::matrix_b, 16, 16, 16, __half, wmma::row_major> fb[2];
#pragma unroll
            for (int i = 0; i < 4; i++)
                wmma::load_matrix_sync(fa[i], &As[wm * 64 + i * 16][kk], 40);
#pragma unroll
            for (int j = 0; j < 2; j++)
                wmma::load_matrix_sync(fb[j], &Bs[kk][wn * 32 + j * 16], 136);
#pragma unroll
            for (int i = 0; i < 4; i++)
#pragma unroll
                for (int j = 0; j < 2; j++)
                    wmma::mma_sync(acc[i][j], fa[i], fb[j], acc[i][j]);
        }
    }

    float* base = CT + (size_t)bm * NG * 128;
#pragma unroll
    for (int i = 0; i < 4; i++)
#pragma unroll
        for (int j = 0; j < 2; j++) {
            const int col = bn * 128 + wn * 32 + j * 16;
            const int b   = wm * 64 + i * 16;
            wmma::store_matrix_sync(base + (size_t)col * 128 + b, acc[i][j],
                                    128, wmma::mem_col_major);
        }
}

// =================================================================================
__global__ void lstm_init()
{
    const int i = blockIdx.x * blockDim.x + threadIdx.x;   // 65536
    if (i == 0) g_count = 0;
    ((uint32_t*)g_h16[0])[i] = 0u;
}

// =================================================================================
// Persistent fp16 HMMA recurrence, WARP-SPECIALIZED + BATCH-SPLIT.
// 128 CTAs = 2 batch-groups x 64 j-groups. CTA owns M=64 batch rows x 16 hidden
// cols (N=64 gate-cols), full K=1024: self-contained tile, no inter-CTA exchange.
// Per-CTA h read = 128 KB/step (chip total 16 MB/step, half of R11).
// Warps 0-7 consumers (tile (mhalf,nposw) x khalf), warps 8-9 producers.
// 2 slot buffers; FULL(s)=1+s, EMPTY(s)=3+s (count 320), consumer bar id 9 (256).
// =================================================================================
__global__ void __launch_bounds__(THR_TOT, 1) lstm_recur(
    const float* __restrict__ Whh,      // [HID, NG]
    const float* __restrict__ gatesT,   // [T][col][b]
    const float* __restrict__ b1, const float* __restrict__ b2,
    __half* __restrict__ seq16,         // layer-0 output (or null)
    float*  __restrict__ seq32,         // last-layer output (or null)
    float* __restrict__ hT, float* __restrict__ cT)
{
    extern __shared__ __align__(16) char smem[];
    __half* Ws   = (__half*)(smem + SM_W);       // [1024][72]
    float*  Gs0  = (float*) (smem + SM_G);       // [64][68]
    float*  Gs1  = Gs0 + 64 * 68;
    float*  bias = (float*) (smem + SM_BIAS);    // [64]
    const uint32_t sbase = smem_u32(smem);

    const int tid = threadIdx.x;
    const int bx  = blockIdx.x;
    const int jg  = bx & 63;            // j-group: hidden cols [jg*16, jg*16+16)
    const int bg  = bx >> 6;            // batch group: rows [bg*64, bg*64+64)
    const int j0  = jg * 16;
    const int m0  = bg * 64;

    // ---- stage W slice (fp16, [1024][72], n = jl*4+gate) + bias, once ----
    for (int idx = tid; idx < 1024 * 64; idx += THR_TOT) {
        const int k = idx >> 6, n = idx & 63;
        const int gate = n & 3, jl = n >> 2;
        Ws[k * 72 + n] = __float2half_rn(Whh[(size_t)k * NG + gate * HID + j0 + jl]);
    }
    if (tid < 64) {
        const int gate = tid & 3, jl = tid >> 2;
        bias[tid] = b1[gate * HID + j0 + jl] + b2[gate * HID + j0 + jl];
    }
    __syncthreads();

    if (tid >= N_CONS) {
        // =========================== PRODUCER WARPS ===========================
        const int ptid = tid - N_CONS;   // 0..63
#pragma unroll 1
        for (int t = 0; t < TSTEPS; ++t) {
            if (t > 0) {
                const unsigned target = (unsigned)t * NCTA_R;
                while (acq_ld(&g_count) < target) { }
            }
            const __half* hin = g_h16[t & 1] + (size_t)m0 * HID;
#pragma unroll 1
            for (int cc = 0; cc < 8; ++cc) {
                const int g = t * 8 + cc;
                const int slot = cc & 1;
                if (g >= 2) BAR_SYNC(3 + slot, THR_TOT);    // wait slot empty
                const uint32_t dbase = sbase + SM_A + slot * SM_ABUF;
                const __half* hp = hin + cc * 128;
#pragma unroll
                for (int u = 0; u < 16; u++) {
                    const int idx = u * 64 + ptid;          // 1024 cp16 total
                    const int row = idx >> 4, k8 = (idx & 15) * 8;
                    cp16(dbase + (uint32_t)(row * 136 + k8) * 2,
                         hp + (size_t)row * HID + k8);
                }
                CP_COMMIT();
                if (cc >= 1) {
                    CP_WAIT1();                             // chunk cc-1 landed
                    BAR_ARRIVE(1 + ((cc - 1) & 1), THR_TOT);
                }
            }
            CP_WAIT0();
            BAR_ARRIVE(1 + (7 & 1), THR_TOT);               // FULL for chunk 7
        }
        return;
    }

    // ============================ CONSUMER WARPS ============================
    const int wid   = tid >> 5;
    const int mhalf = wid & 1;          // rows mhalf*32..+32 (of 64)
    const int nposw = (wid >> 1) & 1;   // cols nposw*32..+32 (of 64)
    const int khalf = wid >> 2;         // 0: kk<64 of chunk, 1: kk>=64

    // cell mapping: thread -> batch row m (0..63), j block jgrp (0..3), 4 j each
    const int m    = tid & 63;
    const int jgrp = tid >> 6;
    float c4[4];
#pragma unroll
    for (int q = 0; q < 4; q++) c4[q] = 0.f;

    // gt prefetch for t = 0
    float gt[16];
    {
        const float* gb = gatesT + (m0 + m);
#pragma unroll
        for (int q = 0; q < 4; q++)
#pragma unroll
            for (int g = 0; g < 4; g++)
                gt[q * 4 + g] = gb[(size_t)(g * HID + j0 + jgrp * 4 + q) * BATCH];
    }

#pragma unroll 1
    for (int t = 0; t < TSTEPS; ++t) {
        __half* hout = g_h16[(t + 1) & 1];

        wmma::fragment<wmma::accumulator, 16, 16, 16, float> acc[2][2];
#pragma unroll
        for (int i = 0; i < 2; i++)
#pragma unroll
            for (int j = 0; j < 2; j++) wmma::fill_fragment(acc[i][j], 0.f);

        // ---- 8 chunks, gated on producer-filled slots ----
#pragma unroll 1
        for (int cc = 0; cc < 8; ++cc) {
            const int slot = cc & 1;
            BAR_SYNC(1 + slot, THR_TOT);    // wait slot full

            const __half* Ap = (const __half*)(smem + SM_A + slot * SM_ABUF)
                             + (size_t)mhalf * 32 * 136 + khalf * 64;
            const __half* Wp = Ws + (size_t)(cc * 128 + khalf * 64) * 72 + nposw * 32;
#pragma unroll
            for (int kk = 0; kk < 64; kk += 16) {
                wmma::fragment<wmma::matrix_a, 16, 16, 16, __half, wmma::row_major> fa[2];
                wmma::fragment<wmma::matrix_b, 16, 16, 16, __half, wmma::row_major> fb[2];
#pragma unroll
                for (int i = 0; i < 2; i++)
                    wmma::load_matrix_sync(fa[i], Ap + (size_t)(i * 16) * 136 + kk, 136);
#pragma unroll
                for (int j = 0; j < 2; j++)
                    wmma::load_matrix_sync(fb[j], Wp + (size_t)kk * 72 + j * 16, 72);
#pragma unroll
                for (int i = 0; i < 2; i++)
#pragma unroll
                    for (int j = 0; j < 2; j++)
                        wmma::mma_sync(acc[i][j], fa[i], fb[j], acc[i][j]);
            }
            BAR_ARRIVE(3 + slot, THR_TOT);  // slot consumed
        }

        // ---- partial gate tiles (64 x 68, per khalf) ----
        float* Gsw = khalf ? Gs1 : Gs0;
#pragma unroll
        for (int i = 0; i < 2; i++)
#pragma unroll
            for (int j = 0; j < 2; j++)
                wmma::store_matrix_sync(Gsw + (size_t)(mhalf * 32 + i * 16) * 68
                                             + nposw * 32 + j * 16,
                                        acc[i][j], 68, wmma::mem_row_major);
        BAR_SYNC(9, N_CONS);

        // ---- LSTM cell: thread (m, jgrp) handles 4 j ----
        float hn[4];
#pragma unroll
        for (int q = 0; q < 4; q++) {
            const int n = jgrp * 16 + q * 4;
            const float4 v0 = *(const float4*)(Gs0 + (size_t)m * 68 + n);
            const float4 v1 = *(const float4*)(Gs1 + (size_t)m * 68 + n);
            const float zi = v0.x + v1.x + gt[q * 4 + 0] + bias[n + 0];
            const float zf = v0.y + v1.y + gt[q * 4 + 1] + bias[n + 1];
            const float zg = v0.z + v1.z + gt[q * 4 + 2] + bias[n + 2];
            const float zo = v0.w + v1.w + gt[q * 4 + 3] + bias[n + 3];
            const float cn = sigf(zf) * c4[q] + sigf(zi) * tanhf(zg);
            hn[q] = sigf(zo) * tanhf(cn);
            c4[q] = cn;
        }

        // ---- publish h, arrive ----
        const size_t ob = (size_t)(m0 + m) * HID + j0 + jgrp * 4;
        const uint2 upk = make_uint2(packh2(hn[0], hn[1]), packh2(hn[2], hn[3]));
        *(uint2*)(hout + ob) = upk;

        BAR_SYNC(9, N_CONS);               // all consumer hout stores done
        if (tid == 0) rel_add1(&g_count);  // release-arrive

        // ---- work shadow ----
        if (seq16) *(uint2*)(seq16 + (size_t)t * BATCH * HID + ob) = upk;
        if (seq32)
            *(float4*)(seq32 + (size_t)t * BATCH * HID + ob) =
                make_float4(hn[0], hn[1], hn[2], hn[3]);
        if (t == TSTEPS - 1) {
            *(float4*)(hT + ob) = make_float4(hn[0], hn[1], hn[2], hn[3]);
            *(float4*)(cT + ob) = make_float4(c4[0], c4[1], c4[2], c4[3]);
        }
        if (t + 1 < TSTEPS) {
            const float* gb = gatesT + (size_t)(t + 1) * NG * BATCH + (m0 + m);
#pragma unroll
            for (int q = 0; q < 4; q++)
#pragma unroll
                for (int g = 0; g < 4; g++)
                    gt[q * 4 + g] = gb[(size_t)(g * HID + j0 + jgrp * 4 + q) * BATCH];
        }
    }
}

// =================================================================================
extern "C" void kernel_launch(void* const* d_in, const int* in_sizes, int n_in,
                              void* d_out, int out_size)
{
    const float* x   = (const float*)d_in[0];
    const float* wih = (const float*)d_in[1];
    const float* whh = (const float*)d_in[2];
    const float* bih = (const float*)d_in[3];
    const float* bhh = (const float*)d_in[4];
    float* out = (float*)d_out;

    cudaFuncSetAttribute(lstm_recur, cudaFuncAttributeMaxDynamicSharedMemorySize, SM_TOTAL);

    float  *gatesT;
    __half *hseq16;
    cudaGetSymbolAddress((void**)&gatesT, g_gatesT);
    cudaGetSymbolAddress((void**)&hseq16, g_hseq16);

    float* hT_base = out + (size_t)TSTEPS * BATCH * HID;
    float* cT_base = hT_base + (size_t)NLAYER * BATCH * HID;

    for (int l = 0; l < NLAYER; ++l) {
        const float* Wih = wih + (size_t)l * 1024 * NG;
        const float* Whh = whh + (size_t)l * HID * NG;
        const float* B1  = bih + (size_t)l * NG;
        const float* B2  = bhh + (size_t)l * NG;
        float* hT = hT_base + (size_t)l * BATCH * HID;
        float* cT = cT_base + (size_t)l * BATCH * HID;

        if (l == 0)
            gemm_input<false><<<dim3(NG / 128, TSTEPS), 256>>>(x, Wih, gatesT);
        else
            gemm_input<true ><<<dim3(NG / 128, TSTEPS), 256>>>(hseq16, Wih, gatesT);

        lstm_init<<<256, 256>>>();

        lstm_recur<<<NCTA_R, THR_TOT, SM_TOTAL>>>(
            Whh, gatesT, B1, B2,
            (l == 0) ? hseq16 : (__half*)nullptr,
            (l == 1) ? out    : (float*)nullptr,
            hT, cT);
    }
}

// round 13
// speedup vs baseline: 1.2952x; 1.1302x over previous
#include <cuda_runtime.h>
#include <cuda_fp16.h>
#include <mma.h>
#include <cstdint>

using namespace nvcuda;

#define TSTEPS 512
#define BATCH  128
#define HID    1024
#define NG     4096
#define NLAYER 2
#define NCTA_R 128
#define THR_TOT 320   // 8 consumer warps + 2 producer warps
#define N_CONS  256

// ---------------- device scratch ----------------
__device__ float  g_gatesT[(size_t)TSTEPS * NG * BATCH];          // [t][col][b]
__device__ __align__(16) __half g_hseq16[(size_t)TSTEPS * BATCH * HID];
__device__ __align__(16) __half g_h16[2][BATCH * HID];            // ping-pong h
__device__ __align__(16) __half g_x16[(size_t)TSTEPS * BATCH * HID];   // fp16 x
__device__ __align__(16) __half g_w16[(size_t)NLAYER * HID * NG];      // fp16 W_ih
__device__ unsigned int g_count;

// ---------------- recurrence smem layout (bytes) ----------------
#define SM_W     0
#define SM_A     147456
#define SM_ABUF  17408
#define SM_G     182272
#define SM_BIAS  217088
#define SM_TOTAL 217344

// ---------------- input-GEMM smem layout (bytes) ----------------
// As: 3 x (128 x 40 half) = 30720 ; Bs: 3 x (32 x 264 half) = 50688
#define GI_A      0
#define GI_ABUF   10240
#define GI_B      30720
#define GI_BBUF   16896
#define GI_TOTAL  81408

__device__ __forceinline__ uint32_t smem_u32(const void* p) {
    uint32_t a;
    asm("{ .reg .u64 t; cvta.to.shared.u64 t, %1; cvt.u32.u64 %0, t; }" : "=r"(a) : "l"(p));
    return a;
}
__device__ __forceinline__ void cp16(uint32_t dst, const void* src) {
    asm volatile("cp.async.cg.shared.global [%0], [%1], 16;" :: "r"(dst), "l"(src));
}
#define CP_COMMIT() asm volatile("cp.async.commit_group;" ::: "memory")
#define CP_WAIT1()  asm volatile("cp.async.wait_group 1;" ::: "memory")
#define CP_WAIT0()  asm volatile("cp.async.wait_group 0;" ::: "memory")

#define BAR_SYNC(id, n)   asm volatile("bar.sync %0, %1;"   :: "r"(id), "r"(n) : "memory")
#define BAR_ARRIVE(id, n) asm volatile("bar.arrive %0, %1;" :: "r"(id), "r"(n) : "memory")

__device__ __forceinline__ void rel_add1(unsigned int* p) {
    asm volatile("red.release.gpu.global.add.u32 [%0], 1;" :: "l"(p) : "memory");
}
__device__ __forceinline__ unsigned int acq_ld(const unsigned int* p) {
    unsigned int v;
    asm volatile("ld.acquire.gpu.global.u32 %0, [%1];" : "=r"(v) : "l"(p) : "memory");
    return v;
}

__device__ __forceinline__ float sigf(float x) { return 1.f / (1.f + __expf(-x)); }
__device__ __forceinline__ uint32_t packh2(float a, float b) {
    return (uint32_t)__half_as_ushort(__float2half_rn(a)) |
           ((uint32_t)__half_as_ushort(__float2half_rn(b)) << 16);
}

// =================================================================================
// fp32 -> fp16 conversion (x and W_ih, once)
// =================================================================================
__global__ void cvt_f32_f16(const float* __restrict__ src, __half* __restrict__ dst)
{
    const size_t i = ((size_t)blockIdx.x * blockDim.x + threadIdx.x) * 4;
    const float4 v = *(const float4*)(src + i);
    *(uint2*)(dst + i) = make_uint2(packh2(v.x, v.y), packh2(v.z, v.w));
}

// =================================================================================
// Input GEMM fp16 (HMMA fp32 accum): CT[t][col][b] = (A[M,1024] @ W16[1024,4096])^T
// CTA tile 128(M=one timestep) x 256(N), BK=32; 8 warps (2m x 4n), warp 64x64.
// cp.async 3-buffer pipeline, 1 syncthreads per chunk.
// =================================================================================
__global__ void __launch_bounds__(256, 1) gemm_input_f16(
    const __half* __restrict__ A,      // [T*B, 1024] fp16
    const __half* __restrict__ W,      // [1024, 4096] fp16
    float* __restrict__ CT)            // [T][col][b]
{
    extern __shared__ __align__(16) char smem[];
    const uint32_t sbase = smem_u32(smem);

    const int tid  = threadIdx.x;
    const int warp = tid >> 5;
    const int wm = warp >> 2;           // 0..1 (M half)
    const int wn = warp & 3;            // 0..3 (N quarter)
    const int bm = blockIdx.y;          // timestep
    const int bn = blockIdx.x;          // 256-col block

    // staging maps
    const int a_row = tid >> 1, a_c8 = (tid & 1) * 16;            // 2 cp16 (A: 512 total)
    const int b_row = tid >> 3, b_c8 = (tid & 7) * 32;            // 4 cp16 (B: 1024 total)

    const __half* Ag = A + (size_t)(bm * 128 + a_row) * HID;
    const __half* Wg = W + (size_t)b_row * NG + bn * 256;

    wmma::fragment<wmma::accumulator, 16, 16, 16, float> acc[4][4];
#pragma unroll
    for (int i = 0; i < 4; i++)
#pragma unroll
        for (int j = 0; j < 4; j++) wmma::fill_fragment(acc[i][j], 0.f);

    // prologue: stage chunks 0,1
#pragma unroll
    for (int c = 0; c < 2; ++c) {
        const uint32_t abase = sbase + GI_A + c * GI_ABUF;
        const uint32_t bbase = sbase + GI_B + c * GI_BBUF;
#pragma unroll
        for (int u = 0; u < 2; u++)
            cp16(abase + (uint32_t)(a_row * 40 + a_c8 + u * 8) * 2,
                 Ag + c * 32 + a_c8 + u * 8);
#pragma unroll
        for (int u = 0; u < 4; u++)
            cp16(bbase + (uint32_t)(b_row * 264 + b_c8 + u * 8) * 2,
                 Wg + (size_t)(c * 32) * NG + b_c8 + u * 8);
        CP_COMMIT();
    }

#pragma unroll 1
    for (int cc = 0; cc < 32; ++cc) {
        if (cc < 31) CP_WAIT1(); else CP_WAIT0();
        __syncthreads();

        if (cc < 30) {  // stage chunk cc+2 into buf (cc+2)%3
            const int cn = cc + 2;
            const uint32_t abase = sbase + GI_A + (cn % 3) * GI_ABUF;
            const uint32_t bbase = sbase + GI_B + (cn % 3) * GI_BBUF;
#pragma unroll
            for (int u = 0; u < 2; u++)
                cp16(abase + (uint32_t)(a_row * 40 + a_c8 + u * 8) * 2,
                     Ag + cn * 32 + a_c8 + u * 8);
#pragma unroll
            for (int u = 0; u < 4; u++)
                cp16(bbase + (uint32_t)(b_row * 264 + b_c8 + u * 8) * 2,
                     Wg + (size_t)(cn * 32) * NG + b_c8 + u * 8);
            CP_COMMIT();
        }

        const __half* As = (const __half*)(smem + GI_A + (cc % 3) * GI_ABUF);
        const __half* Bs = (const __half*)(smem + GI_B + (cc % 3) * GI_BBUF);
#pragma unroll
        for (int kk = 0; kk < 32; kk += 16) {
            wmma::fragment<wmma::matrix_a, 16, 16, 16, __half, wmma::row_major> fa[4];
            wmma::fragment<wmma::matrix_b, 16, 16, 16, __half, wmma::row_major> fb[4];
#pragma unroll
            for (int i = 0; i < 4; i++)
                wmma::load_matrix_sync(fa[i], As + (size_t)(wm * 64 + i * 16) * 40 + kk, 40);
#pragma unroll
            for (int j = 0; j < 4; j++)
                wmma::load_matrix_sync(fb[j], Bs + (size_t)kk * 264 + wn * 64 + j * 16, 264);
#pragma unroll
            for (int i = 0; i < 4; i++)
#pragma unroll
                for (int j = 0; j < 4; j++)
                    wmma::mma_sync(acc[i][j], fa[i], fb[j], acc[i][j]);
        }
    }

    // transposed store: CT[t][col][b]
    float* base = CT + (size_t)bm * NG * 128;
#pragma unroll
    for (int i = 0; i < 4; i++)
#pragma unroll
        for (int j = 0; j < 4; j++) {
            const int col = bn * 256 + wn * 64 + j * 16;
            const int row = wm * 64 + i * 16;
            wmma::store_matrix_sync(base + (size_t)col * 128 + row, acc[i][j],
                                    128, wmma::mem_col_major);
        }
}

// =================================================================================
__global__ void lstm_init()
{
    const int i = blockIdx.x * blockDim.x + threadIdx.x;   // 65536
    if (i == 0) g_count = 0;
    ((uint32_t*)g_h16[0])[i] = 0u;
}

// =================================================================================
// Persistent recurrence (IDENTICAL to round 12 — batch-split + warp-specialized)
// =================================================================================
__global__ void __launch_bounds__(THR_TOT, 1) lstm_recur(
    const float* __restrict__ Whh,      // [HID, NG]
    const float* __restrict__ gatesT,   // [T][col][b]
    const float* __restrict__ b1, const float* __restrict__ b2,
    __half* __restrict__ seq16,         // layer-0 output (or null)
    float*  __restrict__ seq32,         // last-layer output (or null)
    float* __restrict__ hT, float* __restrict__ cT)
{
    extern __shared__ __align__(16) char smem[];
    __half* Ws   = (__half*)(smem + SM_W);       // [1024][72]
    float*  Gs0  = (float*) (smem + SM_G);       // [64][68]
    float*  Gs1  = Gs0 + 64 * 68;
    float*  bias = (float*) (smem + SM_BIAS);    // [64]
    const uint32_t sbase = smem_u32(smem);

    const int tid = threadIdx.x;
    const int bx  = blockIdx.x;
    const int jg  = bx & 63;
    const int bg  = bx >> 6;
    const int j0  = jg * 16;
    const int m0  = bg * 64;

    for (int idx = tid; idx < 1024 * 64; idx += THR_TOT) {
        const int k = idx >> 6, n = idx & 63;
        const int gate = n & 3, jl = n >> 2;
        Ws[k * 72 + n] = __float2half_rn(Whh[(size_t)k * NG + gate * HID + j0 + jl]);
    }
    if (tid < 64) {
        const int gate = tid & 3, jl = tid >> 2;
        bias[tid] = b1[gate * HID + j0 + jl] + b2[gate * HID + j0 + jl];
    }
    __syncthreads();

    if (tid >= N_CONS) {
        // =========================== PRODUCER WARPS ===========================
        const int ptid = tid - N_CONS;
#pragma unroll 1
        for (int t = 0; t < TSTEPS; ++t) {
            if (t > 0) {
                const unsigned target = (unsigned)t * NCTA_R;
                while (acq_ld(&g_count) < target) { }
            }
            const __half* hin = g_h16[t & 1] + (size_t)m0 * HID;
#pragma unroll 1
            for (int cc = 0; cc < 8; ++cc) {
                const int g = t * 8 + cc;
                const int slot = cc & 1;
                if (g >= 2) BAR_SYNC(3 + slot, THR_TOT);
                const uint32_t dbase = sbase + SM_A + slot * SM_ABUF;
                const __half* hp = hin + cc * 128;
#pragma unroll
                for (int u = 0; u < 16; u++) {
                    const int idx = u * 64 + ptid;
                    const int row = idx >> 4, k8 = (idx & 15) * 8;
                    cp16(dbase + (uint32_t)(row * 136 + k8) * 2,
                         hp + (size_t)row * HID + k8);
                }
                CP_COMMIT();
                if (cc >= 1) {
                    CP_WAIT1();
                    BAR_ARRIVE(1 + ((cc - 1) & 1), THR_TOT);
                }
            }
            CP_WAIT0();
            BAR_ARRIVE(1 + (7 & 1), THR_TOT);
        }
        return;
    }

    // ============================ CONSUMER WARPS ============================
    const int wid   = tid >> 5;
    const int mhalf = wid & 1;
    const int nposw = (wid >> 1) & 1;
    const int khalf = wid >> 2;

    const int m    = tid & 63;
    const int jgrp = tid >> 6;
    float c4[4];
#pragma unroll
    for (int q = 0; q < 4; q++) c4[q] = 0.f;

    float gt[16];
    {
        const float* gb = gatesT + (m0 + m);
#pragma unroll
        for (int q = 0; q < 4; q++)
#pragma unroll
            for (int g = 0; g < 4; g++)
                gt[q * 4 + g] = gb[(size_t)(g * HID + j0 + jgrp * 4 + q) * BATCH];
    }

#pragma unroll 1
    for (int t = 0; t < TSTEPS; ++t) {
        __half* hout = g_h16[(t + 1) & 1];

        wmma::fragment<wmma::accumulator, 16, 16, 16, float> acc[2][2];
#pragma unroll
        for (int i = 0; i < 2; i++)
#pragma unroll
            for (int j = 0; j < 2; j++) wmma::fill_fragment(acc[i][j], 0.f);

#pragma unroll 1
        for (int cc = 0; cc < 8; ++cc) {
            const int slot = cc & 1;
            BAR_SYNC(1 + slot, THR_TOT);

            const __half* Ap = (const __half*)(smem + SM_A + slot * SM_ABUF)
                             + (size_t)mhalf * 32 * 136 + khalf * 64;
            const __half* Wp = Ws + (size_t)(cc * 128 + khalf * 64) * 72 + nposw * 32;
#pragma unroll
            for (int kk = 0; kk < 64; kk += 16) {
                wmma::fragment<wmma::matrix_a, 16, 16, 16, __half, wmma::row_major> fa[2];
                wmma::fragment<wmma::matrix_b, 16, 16, 16, __half, wmma::row_major> fb[2];
#pragma unroll
                for (int i = 0; i < 2; i++)
                    wmma::load_matrix_sync(fa[i], Ap + (size_t)(i * 16) * 136 + kk, 136);
#pragma unroll
                for (int j = 0; j < 2; j++)
                    wmma::load_matrix_sync(fb[j], Wp + (size_t)kk * 72 + j * 16, 72);
#pragma unroll
                for (int i = 0; i < 2; i++)
#pragma unroll
                    for (int j = 0; j < 2; j++)
                        wmma::mma_sync(acc[i][j], fa[i], fb[j], acc[i][j]);
            }
            BAR_ARRIVE(3 + slot, THR_TOT);
        }

        float* Gsw = khalf ? Gs1 : Gs0;
#pragma unroll
        for (int i = 0; i < 2; i++)
#pragma unroll
            for (int j = 0; j < 2; j++)
                wmma::store_matrix_sync(Gsw + (size_t)(mhalf * 32 + i * 16) * 68
                                             + nposw * 32 + j * 16,
                                        acc[i][j], 68, wmma::mem_row_major);
        BAR_SYNC(9, N_CONS);

        float hn[4];
#pragma unroll
        for (int q = 0; q < 4; q++) {
            const int n = jgrp * 16 + q * 4;
            const float4 v0 = *(const float4*)(Gs0 + (size_t)m * 68 + n);
            const float4 v1 = *(const float4*)(Gs1 + (size_t)m * 68 + n);
            const float zi = v0.x + v1.x + gt[q * 4 + 0] + bias[n + 0];
            const float zf = v0.y + v1.y + gt[q * 4 + 1] + bias[n + 1];
            const float zg = v0.z + v1.z + gt[q * 4 + 2] + bias[n + 2];
            const float zo = v0.w + v1.w + gt[q * 4 + 3] + bias[n + 3];
            const float cn = sigf(zf) * c4[q] + sigf(zi) * tanhf(zg);
            hn[q] = sigf(zo) * tanhf(cn);
            c4[q] = cn;
        }

        const size_t ob = (size_t)(m0 + m) * HID + j0 + jgrp * 4;
        const uint2 upk = make_uint2(packh2(hn[0], hn[1]), packh2(hn[2], hn[3]));
        *(uint2*)(hout + ob) = upk;

        BAR_SYNC(9, N_CONS);
        if (tid == 0) rel_add1(&g_count);

        if (seq16) *(uint2*)(seq16 + (size_t)t * BATCH * HID + ob) = upk;
        if (seq32)
            *(float4*)(seq32 + (size_t)t * BATCH * HID + ob) =
                make_float4(hn[0], hn[1], hn[2], hn[3]);
        if (t == TSTEPS - 1) {
            *(float4*)(hT + ob) = make_float4(hn[0], hn[1], hn[2], hn[3]);
            *(float4*)(cT + ob) = make_float4(c4[0], c4[1], c4[2], c4[3]);
        }
        if (t + 1 < TSTEPS) {
            const float* gb = gatesT + (size_t)(t + 1) * NG * BATCH + (m0 + m);
#pragma unroll
            for (int q = 0; q < 4; q++)
#pragma unroll
                for (int g = 0; g < 4; g++)
                    gt[q * 4 + g] = gb[(size_t)(g * HID + j0 + jgrp * 4 + q) * BATCH];
        }
    }
}

// =================================================================================
extern "C" void kernel_launch(void* const* d_in, const int* in_sizes, int n_in,
                              void* d_out, int out_size)
{
    const float* x   = (const float*)d_in[0];
    const float* wih = (const float*)d_in[1];
    const float* whh = (const float*)d_in[2];
    const float* bih = (const float*)d_in[3];
    const float* bhh = (const float*)d_in[4];
    float* out = (float*)d_out;

    cudaFuncSetAttribute(lstm_recur, cudaFuncAttributeMaxDynamicSharedMemorySize, SM_TOTAL);
    cudaFuncSetAttribute(gemm_input_f16, cudaFuncAttributeMaxDynamicSharedMemorySize, GI_TOTAL);

    float  *gatesT;
    __half *hseq16, *x16, *w16;
    cudaGetSymbolAddress((void**)&gatesT, g_gatesT);
    cudaGetSymbolAddress((void**)&hseq16, g_hseq16);
    cudaGetSymbolAddress((void**)&x16,    g_x16);
    cudaGetSymbolAddress((void**)&w16,    g_w16);

    float* hT_base = out + (size_t)TSTEPS * BATCH * HID;
    float* cT_base = hT_base + (size_t)NLAYER * BATCH * HID;

    // one-time fp16 conversions
    cvt_f32_f16<<<(TSTEPS * BATCH * HID) / 1024, 256>>>(x, x16);
    cvt_f32_f16<<<(NLAYER * HID * NG) / 1024, 256>>>(wih, w16);

    for (int l = 0; l < NLAYER; ++l) {
        const __half* A16 = l ? hseq16 : x16;
        const __half* W16 = w16 + (size_t)l * HID * NG;
        const float* Whh = whh + (size_t)l * HID * NG;
        const float* B1  = bih + (size_t)l * NG;
        const float* B2  = bhh + (size_t)l * NG;
        float* hT = hT_base + (size_t)l * BATCH * HID;
        float* cT = cT_base + (size_t)l * BATCH * HID;

        gemm_input_f16<<<dim3(NG / 256, TSTEPS), 256, GI_TOTAL>>>(A16, W16, gatesT);

        lstm_init<<<256, 256>>>();

        lstm_recur<<<NCTA_R, THR_TOT, SM_TOTAL>>>(
            Whh, gatesT, B1, B2,
            (l == 0) ? hseq16 : (__half*)nullptr,
            (l == 1) ? out    : (float*)nullptr,
            hT, cT);
    }
}